// round 4
// baseline (speedup 1.0000x reference)
#include <cuda_runtime.h>
#include <cstdint>

// Shapes fixed by the reference: K=64, N=128, T=32768
#define KU   64
#define NU   128
#define EPSV 0.01f
#define INF_BITS 0x7F800000u

// Device-global state. The last retiring block restores these invariants at
// the end of every call, so graph replays stay deterministic.
__device__ unsigned int g_min_bits = INF_BITS;  // running min(mgn) as float bits
__device__ unsigned int g_need     = 0;         // 1 => some block saw min<=0 / slow path
__device__ unsigned int g_done     = 0;         // retired-block counter

__device__ __forceinline__ void atomic_min_float(float val) {
    if (val >= 0.0f) atomicMin((int*)&g_min_bits, __float_as_int(val));
    else             atomicMax(&g_min_bits, __float_as_uint(val));
}

// ---------------------------------------------------------------------------
// Single fused kernel. 256 threads/block, one float4 of t per thread.
// Every block redundantly derives the cubic coefficients from W,b (parallel
// across blocks, so wall cost == one block's cost). Common path has ZERO
// global atomics except one retirement atomicAdd per block; the min/correction
// machinery only activates if a value <= 0 or a slow-path element appears.
// ---------------------------------------------------------------------------
__global__ void __launch_bounds__(256)
fused_mgn_kernel(const float* __restrict__ t,
                 const float* __restrict__ W,
                 const float* __restrict__ b,
                 const float* __restrict__ V,
                 const float* __restrict__ a,
                 float* __restrict__ out,
                 int T, int vlen, int nblocks) {
    __shared__ float sc0[KU], sc1[KU], sc2[KU], sc3[KU];
    __shared__ float scoef[6];   // c0,c1,c2,c3,vsum,a
    __shared__ int   sneg;       // any W or b negative?
    __shared__ float swm[8];
    __shared__ int   sbad[8];
    __shared__ int   slast;
    __shared__ float scorr;

    const int tid  = threadIdx.x;
    const int T4   = T >> 2;
    const int tail = T - (T4 << 2);
    const int i4   = blockIdx.x * 256 + tid;

    if (tid == 0) sneg = 0;

    // ---- Hoisted t load: overlap its DRAM latency with the W/b loads ----
    float4 tv4 = make_float4(0.f, 0.f, 0.f, 0.f);
    const bool have_t = (i4 < T4);
    if (have_t) tv4 = __ldg(&((const float4*)t)[i4]);

    // ---- Phase 1: per-unit sums -> per-k cubic contributions ----
    {
        const int k = tid >> 2, quad = tid & 3;   // 4 threads per unit k
        const float4* W4 = (const float4*)W;
        const float4* B4 = (const float4*)b;
        float s2 = 0.f, sb = 0.f, bb = 0.f;
        bool  neg = false;
        #pragma unroll
        for (int j = 0; j < 8; ++j) {             // 8 float4 = 32 floats each
            const int idx = k * (NU/4) + quad * 8 + j;
            const float4 w  = __ldg(&W4[idx]);
            const float4 bv = __ldg(&B4[idx]);
            #pragma unroll
            for (int c = 0; c < 4; ++c) {
                const float wv = (&w.x)[c], bvv = (&bv.x)[c];
                s2 = fmaf(wv,  wv,  s2);
                sb = fmaf(wv,  bvv, sb);
                bb = fmaf(bvv, bvv, bb);
                neg |= (wv < 0.f) | (bvv < 0.f);
            }
        }
        #pragma unroll
        for (int off = 2; off; off >>= 1) {
            s2 += __shfl_down_sync(0xFFFFFFFFu, s2, off, 4);
            sb += __shfl_down_sync(0xFFFFFFFFu, sb, off, 4);
            bb += __shfl_down_sync(0xFFFFFFFFu, bb, off, 4);
        }
        const unsigned nb = __ballot_sync(0xFFFFFFFFu, neg);
        if ((tid & 31) == 0 && nb) sneg = 1;       // benign smem race, all write 1
        if (quad == 0) {
            sc3[k] = 0.5f * s2 * s2;
            sc2[k] = 1.5f * s2 * sb;
            sc1[k] = fmaf(sb, sb, 0.5f * bb * s2);
            sc0[k] = 0.5f * bb * sb;
        }
    }
    __syncthreads();

    // ---- Phase 2: reduce over k; vsum; a ----
    if (tid < 32) {                                // warp 0: sum 64 -> 1
        float c0 = sc0[tid] + sc0[tid + 32];
        float c1 = sc1[tid] + sc1[tid + 32];
        float c2 = sc2[tid] + sc2[tid + 32];
        float c3 = sc3[tid] + sc3[tid + 32];
        #pragma unroll
        for (int off = 16; off; off >>= 1) {
            c0 += __shfl_down_sync(0xFFFFFFFFu, c0, off);
            c1 += __shfl_down_sync(0xFFFFFFFFu, c1, off);
            c2 += __shfl_down_sync(0xFFFFFFFFu, c2, off);
            c3 += __shfl_down_sync(0xFFFFFFFFu, c3, off);
        }
        if (tid == 0) { scoef[0]=c0; scoef[1]=c1; scoef[2]=c2; scoef[3]=c3; }
    } else if (tid < 64) {                         // warp 1: vsum = sum(V*V)
        const int lid = tid - 32;
        float v = 0.f;
        for (int i = lid; i < vlen; i += 32) v = fmaf(__ldg(&V[i]), __ldg(&V[i]), v);
        #pragma unroll
        for (int off = 16; off; off >>= 1)
            v += __shfl_down_sync(0xFFFFFFFFu, v, off);
        if (lid == 0) scoef[4] = v;
    } else if (tid == 64) {
        scoef[5] = __ldg(a);
    }
    __syncthreads();

    const float c0 = scoef[0], c1 = scoef[1], c2 = scoef[2], c3 = scoef[3];
    const float lin = scoef[4], av = scoef[5];
    const bool wb_nonneg = (sneg == 0);

    // ---- Phase 3: evaluate one float4 of t per thread ----
    float m   = __int_as_float(INF_BITS);
    bool  bad = false;   // slow path used (needs exact min machinery)
    if (have_t) {
        float4 o;
        #pragma unroll
        for (int j = 0; j < 4; ++j) {
            const float tv = (&tv4.x)[j];
            float v;
            if (wb_nonneg && tv >= 0.f) {
                // exact: relu is identity on this element's whole z-column
                v = av + fmaf(lin, tv,
                        fmaf(fmaf(fmaf(c3, tv, c2), tv, c1), tv, c0));
            } else {
                bad = true;
                // exact fallback: brute-force relu network for this element
                float nn = 0.f;
                for (int k = 0; k < KU; ++k) {
                    float prim = 0.f, gate = 0.f;
                    #pragma unroll 8
                    for (int n = 0; n < NU; ++n) {
                        const float wv = __ldg(&W[k * NU + n]);
                        const float bv = __ldg(&b[k * NU + n]);
                        const float r  = fmaxf(fmaf(wv, tv, bv), 0.f);
                        prim = fmaf(r, r, prim);
                        gate = fmaf(wv, r, gate);
                    }
                    nn = fmaf(0.5f * prim, gate, nn);
                }
                v = av + fmaf(lin, tv, nn);
            }
            (&o.x)[j] = v;
            m = fminf(m, v);
        }
        ((float4*)out)[i4] = o;
    }
    // scalar tail (T not multiple of 4) handled by block 0
    if (blockIdx.x == 0 && tid < tail) {
        const int i = (T4 << 2) + tid;
        const float tv = t[i];
        float v;
        if (wb_nonneg && tv >= 0.f) {
            v = av + fmaf(lin, tv, fmaf(fmaf(fmaf(c3, tv, c2), tv, c1), tv, c0));
        } else {
            bad = true;
            float nn = 0.f;
            for (int k = 0; k < KU; ++k) {
                float prim = 0.f, gate = 0.f;
                for (int n = 0; n < NU; ++n) {
                    const float wv = __ldg(&W[k * NU + n]);
                    const float bv = __ldg(&b[k * NU + n]);
                    const float r  = fmaxf(fmaf(wv, tv, bv), 0.f);
                    prim = fmaf(r, r, prim);
                    gate = fmaf(wv, r, gate);
                }
                nn = fmaf(0.5f * prim, gate, nn);
            }
            v = av + fmaf(lin, tv, nn);
        }
        out[i] = v;
        m = fminf(m, v);
    }

    // ---- Phase 4: block min; escalate globally ONLY if it could matter ----
    // A block with min > 0 and no slow-path element cannot influence the
    // correction: if the global min <= 0 it lives in a block with min <= 0,
    // and if the global min > 0 the correction is 0 regardless.
    #pragma unroll
    for (int off = 16; off; off >>= 1)
        m = fminf(m, __shfl_xor_sync(0xFFFFFFFFu, m, off));
    const unsigned wbad = __ballot_sync(0xFFFFFFFFu, bad);
    if ((tid & 31) == 0) { swm[tid >> 5] = m; sbad[tid >> 5] = (wbad != 0); }
    __syncthreads();   // also orders this block's out-stores before the fence

    if (tid == 0) {
        float bm = swm[0];
        int   bb_ = sbad[0];
        #pragma unroll
        for (int w = 1; w < 8; ++w) { bm = fminf(bm, swm[w]); bb_ |= sbad[w]; }
        if (bb_ || bm <= 0.f) {            // rare path: publish exact min
            atomic_min_float(bm);
            atomicOr(&g_need, 1u);
        }
        __threadfence();                              // publish out-stores + min
        const unsigned prev = atomicAdd(&g_done, 1u); // retire
        if (prev == (unsigned)(nblocks - 1)) {
            __threadfence();                          // acquire all blocks' stores
            float corr = 0.f;
            if (*((volatile unsigned*)&g_need) != 0u) {
                const float mn = __uint_as_float(*((volatile unsigned*)&g_min_bits));
                if (mn <= 0.f) corr = EPSV - mn;
            }
            slast = 1; scorr = corr;
        } else {
            slast = 0; scorr = 0.f;
        }
    }
    __syncthreads();

    // ---- Phase 5: last block applies the shift (rare) + resets state ----
    if (slast) {
        const float corr = scorr;
        if (corr != 0.f) {
            for (int i = tid; i < T4; i += 256) {
                float4 v = ((const float4*)out)[i];
                v.x += corr; v.y += corr; v.z += corr; v.w += corr;
                ((float4*)out)[i] = v;
            }
            for (int i = (T4 << 2) + tid; i < T; i += 256)
                out[i] += corr;
        }
        if (tid == 0) {      // restore invariants for the next graph replay
            g_done     = 0;
            g_need     = 0;
            g_min_bits = INF_BITS;
        }
    }
}

// ---------------------------------------------------------------------------
extern "C" void kernel_launch(void* const* d_in, const int* in_sizes, int n_in,
                              void* d_out, int out_size) {
    const float* t = (const float*)d_in[0];
    const float* W = (const float*)d_in[1];
    const float* b = (const float*)d_in[2];
    const float* V = (const float*)d_in[3];
    const float* a = (const float*)d_in[4];
    float* out = (float*)d_out;

    const int T    = in_sizes[0];
    const int vlen = in_sizes[3];

    const int T4 = T >> 2;
    int nblocks = (T4 + 255) / 256;
    if (nblocks < 1) nblocks = 1;

    fused_mgn_kernel<<<nblocks, 256>>>(t, W, b, V, a, out, T, vlen, nblocks);
}